// round 8
// baseline (speedup 1.0000x reference)
#include <cuda_runtime.h>
#include <cuda_bf16.h>
#include <stdint.h>
#include <math.h>

// ESN: B=64, T=256, I=128, R=2048, O=10, alpha=0.5
#define BB 64
#define TT 256
#define II 128
#define RR 2048
#define OO 10
#define NCTA 128
#define NTHR 256

// ---------------- device globals ----------------
__device__ __align__(256) __nv_bfloat16 g_AhiT[RR * RR];  // h2h^T hi
__device__ __align__(256) __nv_bfloat16 g_AloT[RR * RR];  // h2h^T lo
__device__ __align__(256) __nv_bfloat16 g_reshi[BB * RR];
__device__ __align__(256) __nv_bfloat16 g_reslo[BB * RR];
__device__ __align__(256) float g_part[8 * 16 * BB * 128];  // [ks][mt][b][jr]
__device__ __align__(256) unsigned g_arr[NCTA];  // per-CTA arrival flags

// ---------------- smem layout (bytes) ----------------
#define ROWB 528
#define SM_A_HI 0
#define SM_A_LO (128 * ROWB)            // 67584
#define SM_R_HI (2 * 128 * ROWB)        // 135168  (also reused as sP)
#define SM_R_LO (SM_R_HI + 64 * ROWB)   // 168960
#define SM_TOTAL (SM_R_LO + 64 * ROWB)  // 202752

// ---------------- helpers ----------------
static __device__ __forceinline__ unsigned long long dup2(float v) {
    unsigned long long r;
    unsigned u = __float_as_uint(v);
    asm("mov.b64 %0, {%1, %1};" : "=l"(r) : "r"(u));
    return r;
}
static __device__ __forceinline__ void fma2(unsigned long long& a,
                                            unsigned long long x,
                                            unsigned long long y) {
    asm("fma.rn.f32x2 %0, %1, %2, %0;" : "+l"(a) : "l"(x), "l"(y));
}
static __device__ __forceinline__ float lo32(unsigned long long a) {
    return __uint_as_float((unsigned)a);
}
static __device__ __forceinline__ float hi32(unsigned long long a) {
    return __uint_as_float((unsigned)(a >> 32));
}
static __device__ __forceinline__ void mma_bf16(float* d, const unsigned* a,
                                                const unsigned* b) {
    asm volatile(
        "mma.sync.aligned.m16n8k16.row.col.f32.bf16.bf16.f32 "
        "{%0,%1,%2,%3}, {%4,%5,%6,%7}, {%8,%9}, {%0,%1,%2,%3};"
        : "+f"(d[0]), "+f"(d[1]), "+f"(d[2]), "+f"(d[3])
        : "r"(a[0]), "r"(a[1]), "r"(a[2]), "r"(a[3]), "r"(b[0]), "r"(b[1]));
}
// Decentralized flag barrier: each CTA stores its own flag; every CTA's
// warp 0 polls all 128 flags (4 per lane, coalesced). No atomic contention,
// no leader round-trip. Targets are monotonic across graph replays.
static __device__ __forceinline__ void bar_wait(unsigned target, int cta) {
    __syncthreads();
    if (threadIdx.x < 32) {
        if (threadIdx.x == 0) {
            __threadfence();
            asm volatile("st.relaxed.gpu.global.u32 [%0], %1;" ::"l"(
                             &g_arr[cta]),
                         "r"(target)
                         : "memory");
        }
        const unsigned* p = &g_arr[threadIdx.x * 4];
        for (;;) {
            uint4 v;
            asm volatile("ld.volatile.global.v4.u32 {%0,%1,%2,%3}, [%4];"
                         : "=r"(v.x), "=r"(v.y), "=r"(v.z), "=r"(v.w)
                         : "l"(p));
            unsigned mn = min(min(v.x, v.y), min(v.z, v.w));
            if (__all_sync(0xffffffffu, (int)(mn - target) >= 0)) break;
        }
        __threadfence();
    }
    __syncthreads();
}
static __device__ __forceinline__ unsigned pk(float a, float b) {
    __nv_bfloat162 h = __floats2bfloat162_rn(a, b);
    return *(unsigned*)&h;
}

extern "C" __global__ void __launch_bounds__(NTHR, 1)
esn_mma(const float* __restrict__ x, const float* __restrict__ i2h,
        const float* __restrict__ h2h, const float* __restrict__ ow,
        const float* __restrict__ ob, float* __restrict__ out,
        float* __restrict__ hid) {
    extern __shared__ char sm8[];
    const int tid = threadIdx.x;
    const int cta = blockIdx.x;

    // barrier bookkeeping (replay-safe: seed from own flag's current value)
    unsigned barBase;
    {
        volatile unsigned* vp = g_arr;
        barBase = vp[cta];
    }
    unsigned barN = 0;

    // =========== Phase 0: h2h^T hi/lo split (2 x 128x128 tiles/CTA) =======
    {
        float* sT = (float*)sm8;  // 128 x 133 fp32 (68KB)
        for (int rep = 0; rep < 2; rep++) {
            int tt = cta * 2 + rep;
            int ti = tt >> 4, tj = tt & 15;
            __syncthreads();
            for (int idx = tid; idx < 16384; idx += NTHR) {
                int r = idx >> 7, c = idx & 127;
                sT[r * 133 + c] = h2h[(ti * 128 + r) * RR + tj * 128 + c];
            }
            __syncthreads();
            for (int idx = tid; idx < 16384; idx += NTHR) {
                int jl = idx >> 7, kl = idx & 127;
                float v = sT[kl * 133 + jl];  // transpose read
                __nv_bfloat16 bhi = __float2bfloat16_rn(v);
                __nv_bfloat16 blo =
                    __float2bfloat16_rn(v - __bfloat162float(bhi));
                int jg = tj * 128 + jl, kg = ti * 128 + kl;
                g_AhiT[jg * RR + kg] = bhi;
                g_AloT[jg * RR + kg] = blo;
            }
        }
        __syncthreads();
    }

    // =========== Phase A: xin = x @ i2h (SIMT FFMA2, own 16-col slice) ====
    {
        float* sX = (float*)sm8;             // [64][132]
        float* si = (float*)sm8 + 64 * 132;  // [128][16]
        const int j0c = cta * 16;
        for (int i = tid; i < II * 16; i += NTHR) {
            int k = i >> 4, jj = i & 15;
            si[i] = i2h[k * RR + j0c + jj];
        }
        const int row = tid >> 2;
        const int jq = tid & 3;
        for (int rt = 0; rt < BB * TT; rt += 64) {
            __syncthreads();
            for (int i = tid; i < 64 * II / 4; i += NTHR) {
                int r = i >> 5, q = i & 31;
                *(float4*)&sX[r * 132 + q * 4] =
                    *(const float4*)&x[(rt + r) * II + q * 4];
            }
            __syncthreads();
            unsigned long long a0 = 0ull, a1 = 0ull;
#pragma unroll 8
            for (int k = 0; k < II; k++) {
                unsigned long long xv = dup2(sX[row * 132 + k]);
                ulonglong2 hv = *(const ulonglong2*)&si[k * 16 + jq * 4];
                fma2(a0, xv, hv.x);
                fma2(a1, xv, hv.y);
            }
            float4 o = make_float4(lo32(a0), hi32(a0), lo32(a1), hi32(a1));
            *(float4*)&hid[(rt + row) * RR + j0c + jq * 4] = o;
        }
        __syncthreads();
    }
    bar_wait(barBase + (++barN), cta);

    // =========== Stage persistent h2h^T slice into smem ====================
    const int mt = cta & 15;  // j block of 128
    const int ks = cta >> 4;  // k block of 256
    for (int idx = tid; idx < 4096; idx += NTHR) {
        int row = idx >> 5, kc = idx & 31;
        *(uint4*)(sm8 + SM_A_HI + row * ROWB + kc * 16) =
            *(const uint4*)&g_AhiT[(mt * 128 + row) * RR + ks * 256 + kc * 8];
        *(uint4*)(sm8 + SM_A_LO + row * ROWB + kc * 16) =
            *(const uint4*)&g_AloT[(mt * 128 + row) * RR + ks * 256 + kc * 8];
    }
    __syncthreads();

    // =========== Scan ===========
    const int w = tid >> 5;  // all 8 warps do mma
    const int l = tid & 31;
    const int g = l >> 2, tg = l & 3;
    const int mw = w & 3;   // m-pair: m-tiles 2mw, 2mw+1
    const int nh = w >> 2;  // n-half: n-tiles 4nh..4nh+3
    const int gt = cta * NTHR + tid;  // 0..32767
    const int b_e = gt >> 9;          // 0..63
    const int j0 = (gt & 511) * 4;    // 0..2044
    const int mt_e = j0 >> 7, jr0 = j0 & 127;
    float4 p0 = make_float4(0.f, 0.f, 0.f, 0.f);

    const char* sAhi = sm8 + SM_A_HI;
    const char* sAlo = sm8 + SM_A_LO;
    const char* sRhi = sm8 + SM_R_HI;
    const char* sRlo = sm8 + SM_R_LO;
    float* sP = (float*)(sm8 + SM_R_HI);  // [64][132] partial bounce
    const int pbase = (ks * 16 + mt) * 64;

    for (int t = 0; t < TT; t++) {
        float4 xv;
        float4 q = make_float4(0.f, 0.f, 0.f, 0.f);
        if (t > 0) {
            // stage res tile [64][256] hi/lo
            for (int idx = tid; idx < 2048; idx += NTHR) {
                int row = idx >> 5, kc = idx & 31;
                *(uint4*)(sm8 + SM_R_HI + row * ROWB + kc * 16) =
                    *(const uint4*)&g_reshi[row * RR + ks * 256 + kc * 8];
                *(uint4*)(sm8 + SM_R_LO + row * ROWB + kc * 16) =
                    *(const uint4*)&g_reslo[row * RR + ks * 256 + kc * 8];
            }
            __syncthreads();
            float acc[2][4][4];
#pragma unroll
            for (int mi = 0; mi < 2; mi++)
#pragma unroll
                for (int ni = 0; ni < 4; ni++)
#pragma unroll
                    for (int qq = 0; qq < 4; qq++) acc[mi][ni][qq] = 0.f;
#pragma unroll 2
            for (int k16 = 0; k16 < 16; k16++) {
                const int kb = k16 * 32 + 4 * tg;
                unsigned ah[2][4], al[2][4], bh[4][2], bl[4][2];
#pragma unroll
                for (int mi = 0; mi < 2; mi++) {
                    const int rb = (32 * mw + 16 * mi + g) * ROWB;
                    ah[mi][0] = *(const unsigned*)(sAhi + rb + kb);
                    ah[mi][1] = *(const unsigned*)(sAhi + rb + 8 * ROWB + kb);
                    ah[mi][2] = *(const unsigned*)(sAhi + rb + kb + 16);
                    ah[mi][3] =
                        *(const unsigned*)(sAhi + rb + 8 * ROWB + kb + 16);
                    al[mi][0] = *(const unsigned*)(sAlo + rb + kb);
                    al[mi][1] = *(const unsigned*)(sAlo + rb + 8 * ROWB + kb);
                    al[mi][2] = *(const unsigned*)(sAlo + rb + kb + 16);
                    al[mi][3] =
                        *(const unsigned*)(sAlo + rb + 8 * ROWB + kb + 16);
                }
#pragma unroll
                for (int ni = 0; ni < 4; ni++) {
                    const int rb = ((4 * nh + ni) * 8 + g) * ROWB;
                    bh[ni][0] = *(const unsigned*)(sRhi + rb + kb);
                    bh[ni][1] = *(const unsigned*)(sRhi + rb + kb + 16);
                    bl[ni][0] = *(const unsigned*)(sRlo + rb + kb);
                    bl[ni][1] = *(const unsigned*)(sRlo + rb + kb + 16);
                }
#pragma unroll
                for (int mi = 0; mi < 2; mi++)
#pragma unroll
                    for (int ni = 0; ni < 4; ni++)
                        mma_bf16(acc[mi][ni], ah[mi], bh[ni]);
#pragma unroll
                for (int mi = 0; mi < 2; mi++)
#pragma unroll
                    for (int ni = 0; ni < 4; ni++)
                        mma_bf16(acc[mi][ni], ah[mi], bl[ni]);
#pragma unroll
                for (int mi = 0; mi < 2; mi++)
#pragma unroll
                    for (int ni = 0; ni < 4; ni++)
                        mma_bf16(acc[mi][ni], al[mi], bh[ni]);
            }
            __syncthreads();  // res tiles dead; sP overlays SM_R_HI
#pragma unroll
            for (int mi = 0; mi < 2; mi++) {
                const int jr = 32 * mw + 16 * mi + g;
#pragma unroll
                for (int ni = 0; ni < 4; ni++) {
                    const int bc = (4 * nh + ni) * 8 + 2 * tg;
                    sP[bc * 132 + jr] = acc[mi][ni][0];
                    sP[(bc + 1) * 132 + jr] = acc[mi][ni][1];
                    sP[bc * 132 + jr + 8] = acc[mi][ni][2];
                    sP[(bc + 1) * 132 + jr + 8] = acc[mi][ni][3];
                }
            }
            __syncthreads();
            for (int i = tid; i < 2048; i += NTHR) {
                const int b = i >> 5, jq = (i & 31) * 4;
                float4 v = *(const float4*)&sP[b * 132 + jq];
                *(float4*)&g_part[(pbase + b) * 128 + jq] = v;
            }
            // hoist xin load so its latency hides under the barrier
            xv = *(const float4*)&hid[(b_e * TT + t) * RR + j0];
            bar_wait(barBase + (++barN), cta);  // sync1: partials ready
#pragma unroll
            for (int s = 0; s < 8; s++) {
                float4 pa = *(const float4*)
                    &g_part[((s * 16 + mt_e) * 64 + b_e) * 128 + jr0];
                q.x += pa.x; q.y += pa.y; q.z += pa.z; q.w += pa.w;
            }
        } else {
            xv = *(const float4*)&hid[(b_e * TT + t) * RR + j0];
        }
        // ---- epilogue: one float4 (b_e, j0..j0+3) ----
        float4 nr;
        nr.x = 0.5f * p0.x + 0.5f * tanhf(q.x + xv.x);
        nr.y = 0.5f * p0.y + 0.5f * tanhf(q.y + xv.y);
        nr.z = 0.5f * p0.z + 0.5f * tanhf(q.z + xv.z);
        nr.w = 0.5f * p0.w + 0.5f * tanhf(q.w + xv.w);
        p0 = nr;
        *(float4*)&hid[(b_e * TT + t) * RR + j0] = nr;
        float h0 = __bfloat162float(__float2bfloat16_rn(nr.x));
        float h1 = __bfloat162float(__float2bfloat16_rn(nr.y));
        float h2 = __bfloat162float(__float2bfloat16_rn(nr.z));
        float h3 = __bfloat162float(__float2bfloat16_rn(nr.w));
        uint2 uh, ul;
        uh.x = pk(h0, h1);
        uh.y = pk(h2, h3);
        ul.x = pk(nr.x - h0, nr.y - h1);
        ul.y = pk(nr.z - h2, nr.w - h3);
        *(uint2*)&g_reshi[b_e * RR + j0] = uh;
        *(uint2*)&g_reslo[b_e * RR + j0] = ul;
        bar_wait(barBase + (++barN), cta);  // sync2: res ready
    }

    // =========== Readout ===========
    if (cta < BB) {
        const float* res = &hid[(cta * TT + (TT - 1)) * RR];
        float acc[OO];
#pragma unroll
        for (int o = 0; o < OO; o++) acc[o] = 0.f;
        for (int r = tid; r < RR; r += NTHR) {
            float rv = res[r];
#pragma unroll
            for (int o = 0; o < OO; o++) acc[o] += rv * ow[r * OO + o];
        }
        float* red = (float*)sm8;
        __syncthreads();
#pragma unroll
        for (int o = 0; o < OO; o++) red[o * NTHR + tid] = acc[o];
        __syncthreads();
        for (int s2 = NTHR / 2; s2 > 0; s2 >>= 1) {
            if (tid < s2) {
#pragma unroll
                for (int o = 0; o < OO; o++)
                    red[o * NTHR + tid] += red[o * NTHR + tid + s2];
            }
            __syncthreads();
        }
        if (tid < OO) out[cta * OO + tid] = red[tid * NTHR] + ob[tid];
    }
}

extern "C" void kernel_launch(void* const* d_in, const int* in_sizes, int n_in,
                              void* d_out, int out_size) {
    const float* x = (const float*)d_in[0];
    const float* i2h = (const float*)d_in[1];
    const float* h2h = (const float*)d_in[2];
    const float* ow = (const float*)d_in[3];
    const float* ob = (const float*)d_in[4];
    float* out = (float*)d_out;
    float* hid = out + BB * OO;

    cudaFuncSetAttribute(esn_mma, cudaFuncAttributeMaxDynamicSharedMemorySize,
                         SM_TOTAL);
    esn_mma<<<NCTA, NTHR, SM_TOTAL>>>(x, i2h, h2h, ow, ob, out, hid);
}

// round 9
// speedup vs baseline: 1.8932x; 1.8932x over previous
#include <cuda_runtime.h>
#include <cuda_bf16.h>
#include <stdint.h>
#include <math.h>

// ESN: B=64, T=256, I=128, R=2048, O=10, alpha=0.5
#define BB 64
#define TT 256
#define II 128
#define RR 2048
#define OO 10
#define NCTA 128
#define NTHR 256
// exactly 512 barriers per launch -> 65536 counter increments per launch
#define BARS_PER_LAUNCH 512

// ---------------- device globals ----------------
__device__ __align__(256) __nv_bfloat16 g_AhiT[RR * RR];  // h2h^T hi
__device__ __align__(256) __nv_bfloat16 g_AloT[RR * RR];  // h2h^T lo
__device__ __align__(256) __nv_bfloat16 g_reshi[BB * RR];
__device__ __align__(256) __nv_bfloat16 g_reslo[BB * RR];
__device__ __align__(256) float g_part[8 * 16 * BB * 128];  // [ks][mt][b][jr]
__device__ unsigned g_cnt;

// ---------------- smem layout (bytes) ----------------
#define ROWB 528
#define SM_A_HI 0
#define SM_A_LO (128 * ROWB)            // 67584
#define SM_R_HI (2 * 128 * ROWB)        // 135168  (also reused as sP)
#define SM_R_LO (SM_R_HI + 64 * ROWB)   // 168960
#define SM_TOTAL (SM_R_LO + 64 * ROWB)  // 202752

// ---------------- helpers ----------------
static __device__ __forceinline__ unsigned long long dup2(float v) {
    unsigned long long r;
    unsigned u = __float_as_uint(v);
    asm("mov.b64 %0, {%1, %1};" : "=l"(r) : "r"(u));
    return r;
}
static __device__ __forceinline__ void fma2(unsigned long long& a,
                                            unsigned long long x,
                                            unsigned long long y) {
    asm("fma.rn.f32x2 %0, %1, %2, %0;" : "+l"(a) : "l"(x), "l"(y));
}
static __device__ __forceinline__ float lo32(unsigned long long a) {
    return __uint_as_float((unsigned)a);
}
static __device__ __forceinline__ float hi32(unsigned long long a) {
    return __uint_as_float((unsigned)(a >> 32));
}
static __device__ __forceinline__ void mma_bf16(float* d, const unsigned* a,
                                                const unsigned* b) {
    asm volatile(
        "mma.sync.aligned.m16n8k16.row.col.f32.bf16.bf16.f32 "
        "{%0,%1,%2,%3}, {%4,%5,%6,%7}, {%8,%9}, {%0,%1,%2,%3};"
        : "+f"(d[0]), "+f"(d[1]), "+f"(d[2]), "+f"(d[3])
        : "r"(a[0]), "r"(a[1]), "r"(a[2]), "r"(a[3]), "r"(b[0]), "r"(b[1]));
}
// Single-hop barrier: RED (release) arrival + self-poll with acquire load.
// No leader round-trip, no nanosleep. Targets monotonic; wrap-safe compare.
static __device__ __forceinline__ void gbar(unsigned target) {
    __syncthreads();
    if (threadIdx.x == 0) {
        asm volatile("red.release.gpu.global.add.u32 [%0], 1;" ::"l"(&g_cnt)
                     : "memory");
        unsigned v;
        do {
            asm volatile("ld.acquire.gpu.global.u32 %0, [%1];"
                         : "=r"(v)
                         : "l"(&g_cnt));
        } while ((int)(v - target) < 0);
    }
    __syncthreads();
}
static __device__ __forceinline__ unsigned pk(float a, float b) {
    __nv_bfloat162 h = __floats2bfloat162_rn(a, b);
    return *(unsigned*)&h;
}

extern "C" __global__ void __launch_bounds__(NTHR, 1)
esn_mma(const float* __restrict__ x, const float* __restrict__ i2h,
        const float* __restrict__ h2h, const float* __restrict__ ow,
        const float* __restrict__ ob, float* __restrict__ out,
        float* __restrict__ hid) {
    extern __shared__ char sm8[];
    const int tid = threadIdx.x;
    const int cta = blockIdx.x;

    // Barrier base for this launch. At entry g_cnt is within [L*65536,
    // L*65536+127] (no CTA passes barrier 1 before all arrive), so masking
    // to the 65536 boundary recovers the exact launch base.
    unsigned barBase;
    {
        unsigned v;
        asm volatile("ld.relaxed.gpu.global.u32 %0, [%1];"
                     : "=r"(v)
                     : "l"(&g_cnt));
        barBase = v & ~(unsigned)(BARS_PER_LAUNCH * NCTA - 1);
    }
    unsigned barN = 0;

    // =========== Phase 0: h2h^T hi/lo split (2 x 128x128 tiles/CTA) =======
    {
        float* sT = (float*)sm8;  // 128 x 133 fp32 (68KB)
        for (int rep = 0; rep < 2; rep++) {
            int tt = cta * 2 + rep;
            int ti = tt >> 4, tj = tt & 15;
            __syncthreads();
            for (int idx = tid; idx < 16384; idx += NTHR) {
                int r = idx >> 7, c = idx & 127;
                sT[r * 133 + c] = h2h[(ti * 128 + r) * RR + tj * 128 + c];
            }
            __syncthreads();
            for (int idx = tid; idx < 16384; idx += NTHR) {
                int jl = idx >> 7, kl = idx & 127;
                float v = sT[kl * 133 + jl];  // transpose read
                __nv_bfloat16 bhi = __float2bfloat16_rn(v);
                __nv_bfloat16 blo =
                    __float2bfloat16_rn(v - __bfloat162float(bhi));
                int jg = tj * 128 + jl, kg = ti * 128 + kl;
                g_AhiT[jg * RR + kg] = bhi;
                g_AloT[jg * RR + kg] = blo;
            }
        }
        __syncthreads();
    }

    // =========== Phase A: xin = x @ i2h (SIMT FFMA2, own 16-col slice) ====
    {
        float* sX = (float*)sm8;             // [64][132]
        float* si = (float*)sm8 + 64 * 132;  // [128][16]
        const int j0c = cta * 16;
        for (int i = tid; i < II * 16; i += NTHR) {
            int k = i >> 4, jj = i & 15;
            si[i] = i2h[k * RR + j0c + jj];
        }
        const int row = tid >> 2;
        const int jq = tid & 3;
        for (int rt = 0; rt < BB * TT; rt += 64) {
            __syncthreads();
            for (int i = tid; i < 64 * II / 4; i += NTHR) {
                int r = i >> 5, q = i & 31;
                *(float4*)&sX[r * 132 + q * 4] =
                    *(const float4*)&x[(rt + r) * II + q * 4];
            }
            __syncthreads();
            unsigned long long a0 = 0ull, a1 = 0ull;
#pragma unroll 8
            for (int k = 0; k < II; k++) {
                unsigned long long xv = dup2(sX[row * 132 + k]);
                ulonglong2 hv = *(const ulonglong2*)&si[k * 16 + jq * 4];
                fma2(a0, xv, hv.x);
                fma2(a1, xv, hv.y);
            }
            float4 o = make_float4(lo32(a0), hi32(a0), lo32(a1), hi32(a1));
            *(float4*)&hid[(rt + row) * RR + j0c + jq * 4] = o;
        }
        __syncthreads();
    }
    gbar(barBase + NCTA * (++barN));

    // =========== Stage persistent h2h^T slice into smem ====================
    const int mt = cta & 15;  // j block of 128
    const int ks = cta >> 4;  // k block of 256
    for (int idx = tid; idx < 4096; idx += NTHR) {
        int row = idx >> 5, kc = idx & 31;
        *(uint4*)(sm8 + SM_A_HI + row * ROWB + kc * 16) =
            *(const uint4*)&g_AhiT[(mt * 128 + row) * RR + ks * 256 + kc * 8];
        *(uint4*)(sm8 + SM_A_LO + row * ROWB + kc * 16) =
            *(const uint4*)&g_AloT[(mt * 128 + row) * RR + ks * 256 + kc * 8];
    }
    __syncthreads();

    // =========== Scan ===========
    const int w = tid >> 5;  // all 8 warps do mma
    const int l = tid & 31;
    const int g = l >> 2, tg = l & 3;
    const int mw = w & 3;   // m-pair: m-tiles 2mw, 2mw+1
    const int nh = w >> 2;  // n-half: n-tiles 4nh..4nh+3
    const int gt = cta * NTHR + tid;  // 0..32767
    const int b_e = gt >> 9;          // 0..63
    const int j0 = (gt & 511) * 4;    // 0..2044
    const int mt_e = j0 >> 7, jr0 = j0 & 127;
    float4 p0 = make_float4(0.f, 0.f, 0.f, 0.f);

    const char* sAhi = sm8 + SM_A_HI;
    const char* sAlo = sm8 + SM_A_LO;
    const char* sRhi = sm8 + SM_R_HI;
    const char* sRlo = sm8 + SM_R_LO;
    float* sP = (float*)(sm8 + SM_R_HI);  // [64][132] partial bounce
    const int pbase = (ks * 16 + mt) * 64;

    for (int t = 0; t < TT; t++) {
        float4 xv;
        float4 q = make_float4(0.f, 0.f, 0.f, 0.f);
        if (t > 0) {
            // stage res tile [64][256] hi/lo
            for (int idx = tid; idx < 2048; idx += NTHR) {
                int row = idx >> 5, kc = idx & 31;
                *(uint4*)(sm8 + SM_R_HI + row * ROWB + kc * 16) =
                    *(const uint4*)&g_reshi[row * RR + ks * 256 + kc * 8];
                *(uint4*)(sm8 + SM_R_LO + row * ROWB + kc * 16) =
                    *(const uint4*)&g_reslo[row * RR + ks * 256 + kc * 8];
            }
            __syncthreads();
            float acc[2][4][4];
#pragma unroll
            for (int mi = 0; mi < 2; mi++)
#pragma unroll
                for (int ni = 0; ni < 4; ni++)
#pragma unroll
                    for (int qq = 0; qq < 4; qq++) acc[mi][ni][qq] = 0.f;
#pragma unroll 2
            for (int k16 = 0; k16 < 16; k16++) {
                const int kb = k16 * 32 + 4 * tg;
                unsigned ah[2][4], al[2][4], bh[4][2], bl[4][2];
#pragma unroll
                for (int mi = 0; mi < 2; mi++) {
                    const int rb = (32 * mw + 16 * mi + g) * ROWB;
                    ah[mi][0] = *(const unsigned*)(sAhi + rb + kb);
                    ah[mi][1] = *(const unsigned*)(sAhi + rb + 8 * ROWB + kb);
                    ah[mi][2] = *(const unsigned*)(sAhi + rb + kb + 16);
                    ah[mi][3] =
                        *(const unsigned*)(sAhi + rb + 8 * ROWB + kb + 16);
                    al[mi][0] = *(const unsigned*)(sAlo + rb + kb);
                    al[mi][1] = *(const unsigned*)(sAlo + rb + 8 * ROWB + kb);
                    al[mi][2] = *(const unsigned*)(sAlo + rb + kb + 16);
                    al[mi][3] =
                        *(const unsigned*)(sAlo + rb + 8 * ROWB + kb + 16);
                }
#pragma unroll
                for (int ni = 0; ni < 4; ni++) {
                    const int rb = ((4 * nh + ni) * 8 + g) * ROWB;
                    bh[ni][0] = *(const unsigned*)(sRhi + rb + kb);
                    bh[ni][1] = *(const unsigned*)(sRhi + rb + kb + 16);
                    bl[ni][0] = *(const unsigned*)(sRlo + rb + kb);
                    bl[ni][1] = *(const unsigned*)(sRlo + rb + kb + 16);
                }
#pragma unroll
                for (int mi = 0; mi < 2; mi++)
#pragma unroll
                    for (int ni = 0; ni < 4; ni++)
                        mma_bf16(acc[mi][ni], ah[mi], bh[ni]);
#pragma unroll
                for (int mi = 0; mi < 2; mi++)
#pragma unroll
                    for (int ni = 0; ni < 4; ni++)
                        mma_bf16(acc[mi][ni], ah[mi], bl[ni]);
#pragma unroll
                for (int mi = 0; mi < 2; mi++)
#pragma unroll
                    for (int ni = 0; ni < 4; ni++)
                        mma_bf16(acc[mi][ni], al[mi], bh[ni]);
            }
            __syncthreads();  // res tiles dead; sP overlays SM_R_HI
#pragma unroll
            for (int mi = 0; mi < 2; mi++) {
                const int jr = 32 * mw + 16 * mi + g;
#pragma unroll
                for (int ni = 0; ni < 4; ni++) {
                    const int bc = (4 * nh + ni) * 8 + 2 * tg;
                    sP[bc * 132 + jr] = acc[mi][ni][0];
                    sP[(bc + 1) * 132 + jr] = acc[mi][ni][1];
                    sP[bc * 132 + jr + 8] = acc[mi][ni][2];
                    sP[(bc + 1) * 132 + jr + 8] = acc[mi][ni][3];
                }
            }
            __syncthreads();
            for (int i = tid; i < 2048; i += NTHR) {
                const int b = i >> 5, jq = (i & 31) * 4;
                float4 v = *(const float4*)&sP[b * 132 + jq];
                *(float4*)&g_part[(pbase + b) * 128 + jq] = v;
            }
            // hoist xin load so its latency hides under the barrier
            xv = *(const float4*)&hid[(b_e * TT + t) * RR + j0];
            gbar(barBase + NCTA * (++barN));  // sync1: partials ready
#pragma unroll
            for (int s = 0; s < 8; s++) {
                float4 pa = *(const float4*)
                    &g_part[((s * 16 + mt_e) * 64 + b_e) * 128 + jr0];
                q.x += pa.x; q.y += pa.y; q.z += pa.z; q.w += pa.w;
            }
        } else {
            xv = *(const float4*)&hid[(b_e * TT + t) * RR + j0];
        }
        // ---- epilogue: one float4 (b_e, j0..j0+3) ----
        float4 nr;
        nr.x = 0.5f * p0.x + 0.5f * tanhf(q.x + xv.x);
        nr.y = 0.5f * p0.y + 0.5f * tanhf(q.y + xv.y);
        nr.z = 0.5f * p0.z + 0.5f * tanhf(q.z + xv.z);
        nr.w = 0.5f * p0.w + 0.5f * tanhf(q.w + xv.w);
        p0 = nr;
        *(float4*)&hid[(b_e * TT + t) * RR + j0] = nr;
        float h0 = __bfloat162float(__float2bfloat16_rn(nr.x));
        float h1 = __bfloat162float(__float2bfloat16_rn(nr.y));
        float h2 = __bfloat162float(__float2bfloat16_rn(nr.z));
        float h3 = __bfloat162float(__float2bfloat16_rn(nr.w));
        uint2 uh, ul;
        uh.x = pk(h0, h1);
        uh.y = pk(h2, h3);
        ul.x = pk(nr.x - h0, nr.y - h1);
        ul.y = pk(nr.z - h2, nr.w - h3);
        *(uint2*)&g_reshi[b_e * RR + j0] = uh;
        *(uint2*)&g_reslo[b_e * RR + j0] = ul;
        gbar(barBase + NCTA * (++barN));  // sync2: res ready
    }

    // =========== Readout ===========
    if (cta < BB) {
        const float* res = &hid[(cta * TT + (TT - 1)) * RR];
        float acc[OO];
#pragma unroll
        for (int o = 0; o < OO; o++) acc[o] = 0.f;
        for (int r = tid; r < RR; r += NTHR) {
            float rv = res[r];
#pragma unroll
            for (int o = 0; o < OO; o++) acc[o] += rv * ow[r * OO + o];
        }
        float* red = (float*)sm8;
        __syncthreads();
#pragma unroll
        for (int o = 0; o < OO; o++) red[o * NTHR + tid] = acc[o];
        __syncthreads();
        for (int s2 = NTHR / 2; s2 > 0; s2 >>= 1) {
            if (tid < s2) {
#pragma unroll
                for (int o = 0; o < OO; o++)
                    red[o * NTHR + tid] += red[o * NTHR + tid + s2];
            }
            __syncthreads();
        }
        if (tid < OO) out[cta * OO + tid] = red[tid * NTHR] + ob[tid];
    }
}

extern "C" void kernel_launch(void* const* d_in, const int* in_sizes, int n_in,
                              void* d_out, int out_size) {
    const float* x = (const float*)d_in[0];
    const float* i2h = (const float*)d_in[1];
    const float* h2h = (const float*)d_in[2];
    const float* ow = (const float*)d_in[3];
    const float* ob = (const float*)d_in[4];
    float* out = (float*)d_out;
    float* hid = out + BB * OO;

    cudaFuncSetAttribute(esn_mma, cudaFuncAttributeMaxDynamicSharedMemorySize,
                         SM_TOTAL);
    esn_mma<<<NCTA, NTHR, SM_TOTAL>>>(x, i2h, h2h, ow, ob, out, hid);
}

// round 10
// speedup vs baseline: 1.9199x; 1.0141x over previous
#include <cuda_runtime.h>
#include <cuda_bf16.h>
#include <stdint.h>
#include <math.h>

// ESN: B=64, T=256, I=128, R=2048, O=10, alpha=0.5
#define BB 64
#define TT 256
#define II 128
#define RR 2048
#define OO 10
#define NCTA 128
#define NTHR 256
// exactly 512 barriers per launch -> 65536 counter increments per launch
#define BARS_PER_LAUNCH 512

// ---------------- device globals ----------------
__device__ __align__(256) __nv_bfloat16 g_AhiT[RR * RR];  // h2h^T hi
__device__ __align__(256) __nv_bfloat16 g_AloT[RR * RR];  // h2h^T lo
__device__ __align__(256) __nv_bfloat16 g_reshi[BB * RR];
__device__ __align__(256) __nv_bfloat16 g_reslo[BB * RR];
__device__ __align__(256) float g_part[8 * 16 * BB * 128];  // [ks][mt][b][jr]
__device__ __align__(128) unsigned g_cnt;

// ---------------- smem layout (bytes) ----------------
#define ROWB 528
#define SM_A_HI 0
#define SM_A_LO (128 * ROWB)            // 67584
#define SM_R_HI (2 * 128 * ROWB)        // 135168  (also reused as sP)
#define SM_R_LO (SM_R_HI + 64 * ROWB)   // 168960
#define SM_TOTAL (SM_R_LO + 64 * ROWB)  // 202752

// ---------------- helpers ----------------
static __device__ __forceinline__ unsigned long long dup2(float v) {
    unsigned long long r;
    unsigned u = __float_as_uint(v);
    asm("mov.b64 %0, {%1, %1};" : "=l"(r) : "r"(u));
    return r;
}
static __device__ __forceinline__ void fma2(unsigned long long& a,
                                            unsigned long long x,
                                            unsigned long long y) {
    asm("fma.rn.f32x2 %0, %1, %2, %0;" : "+l"(a) : "l"(x), "l"(y));
}
static __device__ __forceinline__ float lo32(unsigned long long a) {
    return __uint_as_float((unsigned)a);
}
static __device__ __forceinline__ float hi32(unsigned long long a) {
    return __uint_as_float((unsigned)(a >> 32));
}
static __device__ __forceinline__ void mma_bf16(float* d, const unsigned* a,
                                                const unsigned* b) {
    asm volatile(
        "mma.sync.aligned.m16n8k16.row.col.f32.bf16.bf16.f32 "
        "{%0,%1,%2,%3}, {%4,%5,%6,%7}, {%8,%9}, {%0,%1,%2,%3};"
        : "+f"(d[0]), "+f"(d[1]), "+f"(d[2]), "+f"(d[3])
        : "r"(a[0]), "r"(a[1]), "r"(a[2]), "r"(a[3]), "r"(b[0]), "r"(b[1]));
}
// Single-hop barrier: RED (release) arrival + self-poll. Relaxed polls with
// nanosleep backoff to keep the hot line uncongested; one acquire to close.
static __device__ __forceinline__ void gbar(unsigned target) {
    __syncthreads();
    if (threadIdx.x == 0) {
        asm volatile("red.release.gpu.global.add.u32 [%0], 1;" ::"l"(&g_cnt)
                     : "memory");
        unsigned v;
        int spins = 0;
        for (;;) {
            asm volatile("ld.relaxed.gpu.global.u32 %0, [%1];"
                         : "=r"(v)
                         : "l"(&g_cnt));
            if ((int)(v - target) >= 0) break;
            if (++spins > 2) __nanosleep(40);
        }
        asm volatile("ld.acquire.gpu.global.u32 %0, [%1];"
                     : "=r"(v)
                     : "l"(&g_cnt));
    }
    __syncthreads();
}
static __device__ __forceinline__ unsigned pk(float a, float b) {
    __nv_bfloat162 h = __floats2bfloat162_rn(a, b);
    return *(unsigned*)&h;
}

extern "C" __global__ void __launch_bounds__(NTHR, 1)
esn_mma(const float* __restrict__ x, const float* __restrict__ i2h,
        const float* __restrict__ h2h, const float* __restrict__ ow,
        const float* __restrict__ ob, float* __restrict__ out,
        float* __restrict__ hid) {
    extern __shared__ char sm8[];
    const int tid = threadIdx.x;
    const int cta = blockIdx.x;

    // Barrier base for this launch (mask to 65536 boundary; at entry the
    // counter is within +127 of the base since no CTA passes barrier 1 early).
    unsigned barBase;
    {
        unsigned v;
        asm volatile("ld.relaxed.gpu.global.u32 %0, [%1];"
                     : "=r"(v)
                     : "l"(&g_cnt));
        barBase = v & ~(unsigned)(BARS_PER_LAUNCH * NCTA - 1);
    }
    unsigned barN = 0;

    // =========== Phase 0: h2h^T hi/lo split (2 x 128x128 tiles/CTA) =======
    {
        float* sT = (float*)sm8;  // 128 x 133 fp32 (68KB)
        for (int rep = 0; rep < 2; rep++) {
            int tt = cta * 2 + rep;
            int ti = tt >> 4, tj = tt & 15;
            __syncthreads();
            for (int idx = tid; idx < 16384; idx += NTHR) {
                int r = idx >> 7, c = idx & 127;
                sT[r * 133 + c] = h2h[(ti * 128 + r) * RR + tj * 128 + c];
            }
            __syncthreads();
            for (int idx = tid; idx < 16384; idx += NTHR) {
                int jl = idx >> 7, kl = idx & 127;
                float v = sT[kl * 133 + jl];  // transpose read
                __nv_bfloat16 bhi = __float2bfloat16_rn(v);
                __nv_bfloat16 blo =
                    __float2bfloat16_rn(v - __bfloat162float(bhi));
                int jg = tj * 128 + jl, kg = ti * 128 + kl;
                g_AhiT[jg * RR + kg] = bhi;
                g_AloT[jg * RR + kg] = blo;
            }
        }
        __syncthreads();
    }

    // =========== Phase A: xin = x @ i2h (SIMT FFMA2, own 16-col slice) ====
    {
        float* sX = (float*)sm8;             // [64][132]
        float* si = (float*)sm8 + 64 * 132;  // [128][16]
        const int j0c = cta * 16;
        for (int i = tid; i < II * 16; i += NTHR) {
            int k = i >> 4, jj = i & 15;
            si[i] = i2h[k * RR + j0c + jj];
        }
        const int row = tid >> 2;
        const int jq = tid & 3;
        for (int rt = 0; rt < BB * TT; rt += 64) {
            __syncthreads();
            for (int i = tid; i < 64 * II / 4; i += NTHR) {
                int r = i >> 5, q = i & 31;
                *(float4*)&sX[r * 132 + q * 4] =
                    *(const float4*)&x[(rt + r) * II + q * 4];
            }
            __syncthreads();
            unsigned long long a0 = 0ull, a1 = 0ull;
#pragma unroll 8
            for (int k = 0; k < II; k++) {
                unsigned long long xv = dup2(sX[row * 132 + k]);
                ulonglong2 hv = *(const ulonglong2*)&si[k * 16 + jq * 4];
                fma2(a0, xv, hv.x);
                fma2(a1, xv, hv.y);
            }
            float4 o = make_float4(lo32(a0), hi32(a0), lo32(a1), hi32(a1));
            *(float4*)&hid[(rt + row) * RR + j0c + jq * 4] = o;
        }
        __syncthreads();
    }
    gbar(barBase + NCTA * (++barN));

    // =========== Stage persistent h2h^T slice into smem ====================
    const int mt = cta & 15;  // j block of 128
    const int ks = cta >> 4;  // k block of 256
    for (int idx = tid; idx < 4096; idx += NTHR) {
        int row = idx >> 5, kc = idx & 31;
        *(uint4*)(sm8 + SM_A_HI + row * ROWB + kc * 16) =
            *(const uint4*)&g_AhiT[(mt * 128 + row) * RR + ks * 256 + kc * 8];
        *(uint4*)(sm8 + SM_A_LO + row * ROWB + kc * 16) =
            *(const uint4*)&g_AloT[(mt * 128 + row) * RR + ks * 256 + kc * 8];
    }
    __syncthreads();

    // =========== Scan ===========
    const int w = tid >> 5;  // all 8 warps do mma
    const int l = tid & 31;
    const int g = l >> 2, tg = l & 3;
    const int mw = w & 3;   // m-pair: m-tiles 2mw, 2mw+1
    const int nh = w >> 2;  // n-half: n-tiles 4nh..4nh+3 (b 32nh..32nh+31)
    const int tidh = tid - nh * 128;  // 0..127 within half-group
    const int gt = cta * NTHR + tid;  // 0..32767
    const int b_e = gt >> 9;          // 0..63
    const int j0 = (gt & 511) * 4;    // 0..2044
    const int mt_e = j0 >> 7, jr0 = j0 & 127;
    float4 p0 = make_float4(0.f, 0.f, 0.f, 0.f);
    float4 pend;  // deferred hid store (valid when t>0 at loop top)

    const char* sAhi = sm8 + SM_A_HI;
    const char* sAlo = sm8 + SM_A_LO;
    const char* sRhi = sm8 + SM_R_HI;
    const char* sRlo = sm8 + SM_R_LO;
    float* sP = (float*)(sm8 + SM_R_HI);  // [64][132] partial bounce
    const int pbase = (ks * 16 + mt) * 64;

    for (int t = 0; t < TT; t++) {
        float4 xv;
        float4 q = make_float4(0.f, 0.f, 0.f, 0.f);
        if (t > 0) {
            // stage res tile [64][256] hi/lo
            for (int idx = tid; idx < 2048; idx += NTHR) {
                int row = idx >> 5, kc = idx & 31;
                *(uint4*)(sm8 + SM_R_HI + row * ROWB + kc * 16) =
                    *(const uint4*)&g_reshi[row * RR + ks * 256 + kc * 8];
                *(uint4*)(sm8 + SM_R_LO + row * ROWB + kc * 16) =
                    *(const uint4*)&g_reslo[row * RR + ks * 256 + kc * 8];
            }
            // deferred hid store for step t-1 (own element; nobody else reads)
            *(float4*)&hid[(b_e * TT + (t - 1)) * RR + j0] = pend;
            __syncthreads();
            float acc[2][4][4];
#pragma unroll
            for (int mi = 0; mi < 2; mi++)
#pragma unroll
                for (int ni = 0; ni < 4; ni++)
#pragma unroll
                    for (int qq = 0; qq < 4; qq++) acc[mi][ni][qq] = 0.f;
#pragma unroll 2
            for (int k16 = 0; k16 < 16; k16++) {
                const int kb = k16 * 32 + 4 * tg;
                unsigned ah[2][4], al[2][4], bh[4][2], bl[4][2];
#pragma unroll
                for (int mi = 0; mi < 2; mi++) {
                    const int rb = (32 * mw + 16 * mi + g) * ROWB;
                    ah[mi][0] = *(const unsigned*)(sAhi + rb + kb);
                    ah[mi][1] = *(const unsigned*)(sAhi + rb + 8 * ROWB + kb);
                    ah[mi][2] = *(const unsigned*)(sAhi + rb + kb + 16);
                    ah[mi][3] =
                        *(const unsigned*)(sAhi + rb + 8 * ROWB + kb + 16);
                    al[mi][0] = *(const unsigned*)(sAlo + rb + kb);
                    al[mi][1] = *(const unsigned*)(sAlo + rb + 8 * ROWB + kb);
                    al[mi][2] = *(const unsigned*)(sAlo + rb + kb + 16);
                    al[mi][3] =
                        *(const unsigned*)(sAlo + rb + 8 * ROWB + kb + 16);
                }
#pragma unroll
                for (int ni = 0; ni < 4; ni++) {
                    const int rb = ((4 * nh + ni) * 8 + g) * ROWB;
                    bh[ni][0] = *(const unsigned*)(sRhi + rb + kb);
                    bh[ni][1] = *(const unsigned*)(sRhi + rb + kb + 16);
                    bl[ni][0] = *(const unsigned*)(sRlo + rb + kb);
                    bl[ni][1] = *(const unsigned*)(sRlo + rb + kb + 16);
                }
#pragma unroll
                for (int mi = 0; mi < 2; mi++)
#pragma unroll
                    for (int ni = 0; ni < 4; ni++)
                        mma_bf16(acc[mi][ni], ah[mi], bh[ni]);
#pragma unroll
                for (int mi = 0; mi < 2; mi++)
#pragma unroll
                    for (int ni = 0; ni < 4; ni++)
                        mma_bf16(acc[mi][ni], ah[mi], bl[ni]);
#pragma unroll
                for (int mi = 0; mi < 2; mi++)
#pragma unroll
                    for (int ni = 0; ni < 4; ni++)
                        mma_bf16(acc[mi][ni], al[mi], bh[ni]);
            }
            // per-half join: each half's sP rows overlay exactly the sRhi
            // rows only that half reads (b 32nh..32nh+31) -> disjoint.
            {
                const int bid = 1 + nh;
                asm volatile("bar.sync %0, %1;" ::"r"(bid), "r"(128)
                             : "memory");
#pragma unroll
                for (int mi = 0; mi < 2; mi++) {
                    const int jr = 32 * mw + 16 * mi + g;
#pragma unroll
                    for (int ni = 0; ni < 4; ni++) {
                        const int bc = (4 * nh + ni) * 8 + 2 * tg;
                        sP[bc * 132 + jr] = acc[mi][ni][0];
                        sP[(bc + 1) * 132 + jr] = acc[mi][ni][1];
                        sP[bc * 132 + jr + 8] = acc[mi][ni][2];
                        sP[(bc + 1) * 132 + jr + 8] = acc[mi][ni][3];
                    }
                }
                asm volatile("bar.sync %0, %1;" ::"r"(bid), "r"(128)
                             : "memory");
                // this half copies its own b-rows out (coalesced)
                for (int i = tidh; i < 1024; i += 128) {
                    const int b = nh * 32 + (i >> 5), jq = (i & 31) * 4;
                    float4 v = *(const float4*)&sP[b * 132 + jq];
                    *(float4*)&g_part[(pbase + b) * 128 + jq] = v;
                }
            }
            // hoist xin load so its latency hides under the barrier
            xv = *(const float4*)&hid[(b_e * TT + t) * RR + j0];
            gbar(barBase + NCTA * (++barN));  // sync1: partials ready
#pragma unroll
            for (int s = 0; s < 8; s++) {
                float4 pa = *(const float4*)
                    &g_part[((s * 16 + mt_e) * 64 + b_e) * 128 + jr0];
                q.x += pa.x; q.y += pa.y; q.z += pa.z; q.w += pa.w;
            }
        } else {
            xv = *(const float4*)&hid[(b_e * TT + t) * RR + j0];
        }
        // ---- epilogue: one float4 (b_e, j0..j0+3) ----
        float4 nr;
        nr.x = 0.5f * p0.x + 0.5f * tanhf(q.x + xv.x);
        nr.y = 0.5f * p0.y + 0.5f * tanhf(q.y + xv.y);
        nr.z = 0.5f * p0.z + 0.5f * tanhf(q.z + xv.z);
        nr.w = 0.5f * p0.w + 0.5f * tanhf(q.w + xv.w);
        p0 = nr;
        if (t == TT - 1) {
            *(float4*)&hid[(b_e * TT + t) * RR + j0] = nr;  // readout needs it
        } else {
            pend = nr;  // deferred to next iteration (past gbar2)
        }
        float h0 = __bfloat162float(__float2bfloat16_rn(nr.x));
        float h1 = __bfloat162float(__float2bfloat16_rn(nr.y));
        float h2 = __bfloat162float(__float2bfloat16_rn(nr.z));
        float h3 = __bfloat162float(__float2bfloat16_rn(nr.w));
        uint2 uh, ul;
        uh.x = pk(h0, h1);
        uh.y = pk(h2, h3);
        ul.x = pk(nr.x - h0, nr.y - h1);
        ul.y = pk(nr.z - h2, nr.w - h3);
        *(uint2*)&g_reshi[b_e * RR + j0] = uh;
        *(uint2*)&g_reslo[b_e * RR + j0] = ul;
        gbar(barBase + NCTA * (++barN));  // sync2: res ready
    }

    // =========== Readout ===========
    if (cta < BB) {
        const float* res = &hid[(cta * TT + (TT - 1)) * RR];
        float acc[OO];
#pragma unroll
        for (int o = 0; o < OO; o++) acc[o] = 0.f;
        for (int r = tid; r < RR; r += NTHR) {
            float rv = res[r];
#pragma unroll
            for (int o = 0; o < OO; o++) acc[o] += rv * ow[r * OO + o];
        }
        float* red = (float*)sm8;
        __syncthreads();
#pragma unroll
        for (int o = 0; o < OO; o++) red[o * NTHR + tid] = acc[o];
        __syncthreads();
        for (int s2 = NTHR / 2; s2 > 0; s2 >>= 1) {
            if (tid < s2) {
#pragma unroll
                for (int o = 0; o < OO; o++)
                    red[o * NTHR + tid] += red[o * NTHR + tid + s2];
            }
            __syncthreads();
        }
        if (tid < OO) out[cta * OO + tid] = red[tid * NTHR] + ob[tid];
    }
}

extern "C" void kernel_launch(void* const* d_in, const int* in_sizes, int n_in,
                              void* d_out, int out_size) {
    const float* x = (const float*)d_in[0];
    const float* i2h = (const float*)d_in[1];
    const float* h2h = (const float*)d_in[2];
    const float* ow = (const float*)d_in[3];
    const float* ob = (const float*)d_in[4];
    float* out = (float*)d_out;
    float* hid = out + BB * OO;

    cudaFuncSetAttribute(esn_mma, cudaFuncAttributeMaxDynamicSharedMemorySize,
                         SM_TOTAL);
    esn_mma<<<NCTA, NTHR, SM_TOTAL>>>(x, i2h, h2h, ow, ob, out, hid);
}